// round 6
// baseline (speedup 1.0000x reference)
#include <cuda_runtime.h>
#include <math.h>

#define BATCH 8
#define CHAN 128
#define PLANE 65536          // D*H*W = 4*128*128
#define NBC (BATCH * CHAN)   // 1024

__device__ float g_max[NBC];

// ---------------------------------------------------------------------------
// Kernel 1: per-(b,c) global max (verified 40.4us, 84% of HBM spec).
// ---------------------------------------------------------------------------
__global__ __launch_bounds__(512) void reduce_max_kernel(const float* __restrict__ x) {
    const int bc = blockIdx.x;
    const float4* p = reinterpret_cast<const float4*>(x) + (size_t)bc * (PLANE / 4);
    const int tid = threadIdx.x;

    float m0 = -INFINITY, m1 = -INFINITY;
    #pragma unroll 4
    for (int i = tid; i < PLANE / 4; i += 1024) {
        float4 a = __ldcs(p + i);
        float4 b = __ldcs(p + i + 512);
        m0 = fmaxf(m0, fmaxf(fmaxf(a.x, a.y), fmaxf(a.z, a.w)));
        m1 = fmaxf(m1, fmaxf(fmaxf(b.x, b.y), fmaxf(b.z, b.w)));
    }
    float m = fmaxf(m0, m1);

    #pragma unroll
    for (int off = 16; off > 0; off >>= 1)
        m = fmaxf(m, __shfl_xor_sync(0xffffffffu, m, off));

    __shared__ float sm[16];
    if ((tid & 31) == 0) sm[tid >> 5] = m;
    __syncthreads();
    if (tid < 16) {
        m = sm[tid];
        #pragma unroll
        for (int off = 8; off > 0; off >>= 1)
            m = fmaxf(m, __shfl_xor_sync(0x0000ffffu, m, off));
        if (tid == 0) g_max[bc] = m;
    }
}

// ---------------------------------------------------------------------------
// Kernel 2: fused gate + scale.  2 blocks per (b,c) plane, 256 threads,
// 32 float4 per thread (4 chunks of 8 front-batched streaming loads).
//
// Prologue (per block, redundant but cheap): compute THIS block's gate value.
//   gp[b][:] (128 floats, L2)  ->  h = relu(W1 gp + b1)  (threads 0..127,
//   one hidden unit each, w1 rows stay hot in L2 after the first wave)
//   ->  gate_c = sigmoid(b2[c] + dot(w2[c,:], h))  (warp 0).
// This removes the single-block mlp kernel node and its ~20us of serialized
// latency + wave transitions.
// ---------------------------------------------------------------------------
__global__ __launch_bounds__(256) void gate_scale_kernel(const float* __restrict__ x,
                                                         const float* __restrict__ w1,
                                                         const float* __restrict__ b1,
                                                         const float* __restrict__ w2,
                                                         const float* __restrict__ b2,
                                                         float* __restrict__ out) {
    const int tid = threadIdx.x;
    const int bc  = blockIdx.x >> 1;        // 2 blocks per plane
    const int b   = bc >> 7;
    const int c   = bc & 127;

    __shared__ float gp[CHAN];
    __shared__ float hs[CHAN];
    __shared__ float s_gate;

    // --- prologue: gate for (b, c) ---
    if (tid < CHAN)
        gp[tid] = __ldg(&g_max[b * CHAN + tid]);
    __syncthreads();

    if (tid < CHAN) {
        float acc = __ldg(&b1[tid]);
        const float4* wrow = reinterpret_cast<const float4*>(w1 + (size_t)tid * CHAN);
        #pragma unroll 8
        for (int q = 0; q < CHAN / 4; q++) {
            float4 w = __ldg(wrow + q);
            const int k = q * 4;
            acc = fmaf(gp[k],     w.x, acc);
            acc = fmaf(gp[k + 1], w.y, acc);
            acc = fmaf(gp[k + 2], w.z, acc);
            acc = fmaf(gp[k + 3], w.w, acc);
        }
        hs[tid] = fmaxf(acc, 0.0f);
    }
    __syncthreads();

    if (tid < 32) {
        const float4 w = __ldg(reinterpret_cast<const float4*>(w2 + (size_t)c * CHAN) + tid);
        const int k = tid * 4;
        float s = hs[k] * w.x + hs[k + 1] * w.y + hs[k + 2] * w.z + hs[k + 3] * w.w;
        #pragma unroll
        for (int off = 16; off > 0; off >>= 1)
            s += __shfl_xor_sync(0xffffffffu, s, off);
        if (tid == 0)
            s_gate = 1.0f / (1.0f + expf(-(s + __ldg(&b2[c]))));
    }
    __syncthreads();
    const float g = s_gate;

    // --- streaming scale: 8192 consecutive float4 per block ---
    const float4* xp = reinterpret_cast<const float4*>(x);
    float4* op = reinterpret_cast<float4*>(out);
    const size_t blk = (size_t)blockIdx.x * 8192 + tid;

    #pragma unroll
    for (int ch = 0; ch < 4; ch++) {
        const size_t base = blk + (size_t)ch * 2048;
        float4 v[8];
        #pragma unroll
        for (int k = 0; k < 8; k++)
            v[k] = __ldcs(xp + base + (size_t)k * 256);
        #pragma unroll
        for (int k = 0; k < 8; k++) {
            v[k].x *= g; v[k].y *= g; v[k].z *= g; v[k].w *= g;
            __stcs(op + base + (size_t)k * 256, v[k]);
        }
    }
}

// ---------------------------------------------------------------------------
extern "C" void kernel_launch(void* const* d_in, const int* in_sizes, int n_in,
                              void* d_out, int out_size) {
    const float* x  = (const float*)d_in[0];
    const float* w1 = (const float*)d_in[1];
    const float* b1 = (const float*)d_in[2];
    const float* w2 = (const float*)d_in[3];
    const float* b2 = (const float*)d_in[4];
    float* out = (float*)d_out;

    reduce_max_kernel<<<NBC, 512>>>(x);
    // 16,777,216 float4 total -> 2048 blocks x (256 threads x 32 f4)
    gate_scale_kernel<<<2048, 256>>>(x, w1, b1, w2, b2, out);
}

// round 7
// speedup vs baseline: 1.1594x; 1.1594x over previous
#include <cuda_runtime.h>
#include <math.h>

#define BATCH 8
#define CHAN 128
#define PLANE 65536          // D*H*W = 4*128*128
#define NBC (BATCH * CHAN)   // 1024

__device__ float g_max[NBC];
__device__ float g_hid[NBC];   // hidden layer h[b][o]

// ---------------------------------------------------------------------------
// Kernel 1: per-(b,c) global max (verified 40.4us, 84% of HBM spec).
// ---------------------------------------------------------------------------
__global__ __launch_bounds__(512) void reduce_max_kernel(const float* __restrict__ x) {
    const int bc = blockIdx.x;
    const float4* p = reinterpret_cast<const float4*>(x) + (size_t)bc * (PLANE / 4);
    const int tid = threadIdx.x;

    float m0 = -INFINITY, m1 = -INFINITY;
    #pragma unroll 4
    for (int i = tid; i < PLANE / 4; i += 1024) {
        float4 a = __ldcs(p + i);
        float4 b = __ldcs(p + i + 512);
        m0 = fmaxf(m0, fmaxf(fmaxf(a.x, a.y), fmaxf(a.z, a.w)));
        m1 = fmaxf(m1, fmaxf(fmaxf(b.x, b.y), fmaxf(b.z, b.w)));
    }
    float m = fmaxf(m0, m1);

    #pragma unroll
    for (int off = 16; off > 0; off >>= 1)
        m = fmaxf(m, __shfl_xor_sync(0xffffffffu, m, off));

    __shared__ float sm[16];
    if ((tid & 31) == 0) sm[tid >> 5] = m;
    __syncthreads();
    if (tid < 16) {
        m = sm[tid];
        #pragma unroll
        for (int off = 8; off > 0; off >>= 1)
            m = fmaxf(m, __shfl_xor_sync(0x0000ffffu, m, off));
        if (tid == 0) g_max[bc] = m;
    }
}

// ---------------------------------------------------------------------------
// Kernel 2: hidden layer h[b][o] = relu(b1[o] + dot(w1[o,:], gp[b,:])).
// 8 blocks (one per batch) x 128 threads (one per hidden unit).
// 8x the parallelism of the old single-block mlp; w1 rows read once per
// batch-block (L2-shared across the 8 blocks).
// ---------------------------------------------------------------------------
__global__ __launch_bounds__(128) void hidden_kernel(const float* __restrict__ w1,
                                                     const float* __restrict__ b1) {
    const int b = blockIdx.x;
    const int o = threadIdx.x;

    __shared__ float gp[CHAN];
    gp[o] = g_max[b * CHAN + o];
    __syncthreads();

    float acc = __ldg(&b1[o]);
    const float4* wrow = reinterpret_cast<const float4*>(w1 + (size_t)o * CHAN);
    #pragma unroll 8
    for (int q = 0; q < CHAN / 4; q++) {
        float4 w = __ldg(wrow + q);
        const int k = q * 4;
        acc = fmaf(gp[k],     w.x, acc);
        acc = fmaf(gp[k + 1], w.y, acc);
        acc = fmaf(gp[k + 2], w.z, acc);
        acc = fmaf(gp[k + 3], w.w, acc);
    }
    g_hid[b * CHAN + o] = fmaxf(acc, 0.0f);
}

// ---------------------------------------------------------------------------
// Kernel 3: fused (cheap) gate + streaming scale.
// 8192 blocks (8 per plane) x 256 threads x 8 float4 — the exact verified
// 75.5us streaming structure. Prologue: warp 0 computes
//   gate = sigmoid(b2[c] + dot(w2[c,:], h[b,:]))
// = two 512B L2-hot loads + 128 MACs (~0.3us, overlapped across waves).
// ---------------------------------------------------------------------------
__global__ __launch_bounds__(256) void gate_scale_kernel(const float* __restrict__ x,
                                                         const float* __restrict__ w2,
                                                         const float* __restrict__ b2,
                                                         float* __restrict__ out) {
    const int tid = threadIdx.x;
    const int bc  = blockIdx.x >> 3;        // 8 blocks per plane
    const int b   = bc >> 7;
    const int c   = bc & 127;

    __shared__ float s_gate;

    if (tid < 32) {
        const float4 w = __ldg(reinterpret_cast<const float4*>(w2 + (size_t)c * CHAN) + tid);
        const float4 h = __ldg(reinterpret_cast<const float4*>(g_hid + (size_t)b * CHAN) + tid);
        float s = h.x * w.x + h.y * w.y + h.z * w.z + h.w * w.w;
        #pragma unroll
        for (int off = 16; off > 0; off >>= 1)
            s += __shfl_xor_sync(0xffffffffu, s, off);
        if (tid == 0)
            s_gate = 1.0f / (1.0f + expf(-(s + __ldg(&b2[c]))));
    }
    __syncthreads();
    const float g = s_gate;

    const size_t base = (size_t)blockIdx.x * 2048 + tid;
    const float4* xp = reinterpret_cast<const float4*>(x);
    float4* op = reinterpret_cast<float4*>(out);

    float4 v[8];
    #pragma unroll
    for (int k = 0; k < 8; k++)
        v[k] = __ldcs(xp + base + (size_t)k * 256);

    #pragma unroll
    for (int k = 0; k < 8; k++) {
        v[k].x *= g; v[k].y *= g; v[k].z *= g; v[k].w *= g;
        __stcs(op + base + (size_t)k * 256, v[k]);
    }
}

// ---------------------------------------------------------------------------
extern "C" void kernel_launch(void* const* d_in, const int* in_sizes, int n_in,
                              void* d_out, int out_size) {
    const float* x  = (const float*)d_in[0];
    const float* w1 = (const float*)d_in[1];
    const float* b1 = (const float*)d_in[2];
    const float* w2 = (const float*)d_in[3];
    const float* b2 = (const float*)d_in[4];
    float* out = (float*)d_out;

    reduce_max_kernel<<<NBC, 512>>>(x);
    hidden_kernel<<<BATCH, 128>>>(w1, b1);
    gate_scale_kernel<<<8192, 256>>>(x, w2, b2, out);
}